// round 4
// baseline (speedup 1.0000x reference)
#include <cuda_runtime.h>

// Problem constants
#define TS   1000
#define BTOT 2048
#define HE   64     // encoder hidden
#define HD   65     // decoder hidden
#define GE   256    // 4*HE
#define GD   260    // 4*HD
#define NB   7      // batch elements per block (296 blocks = 2*148 SMs, balanced)
#define NGRID 296
#define NTH  256    // threads per block
#define HSTR 68     // h row stride (16B-aligned rows, banks 4*bb+k -> conflict-free)

typedef unsigned long long u64;

__device__ __forceinline__ u64 pack2(float lo, float hi){
    u64 r; asm("mov.b64 %0, {%1, %2};" : "=l"(r) : "f"(lo), "f"(hi)); return r;
}
__device__ __forceinline__ float2 unpk(u64 v){
    float2 f; asm("mov.b64 {%0, %1}, %2;" : "=f"(f.x), "=f"(f.y) : "l"(v)); return f;
}
__device__ __forceinline__ u64 ffma2(u64 a, u64 b, u64 c){
    u64 d; asm("fma.rn.f32x2 %0, %1, %2, %3;" : "=l"(d) : "l"(a), "l"(b), "l"(c)); return d;
}
// accurate sigmoid (recurrent path: i, f gates)
__device__ __forceinline__ float sigf(float x){
    return __fdividef(1.0f, 1.0f + __expf(-x));
}
// accurate tanh (recurrent path: g gate)
__device__ __forceinline__ float tanhf_(float x){
    return fmaf(2.0f, sigf(2.0f * x), -1.0f);
}
// fast tanh via MUFU.TANH (non-recurrent path only)
__device__ __forceinline__ float tanha(float x){
    float y; asm("tanh.approx.f32 %0, %1;" : "=f"(y) : "f"(x)); return y;
}
// fast sigmoid via MUFU.TANH (o gate only)
__device__ __forceinline__ float siga(float x){
    return fmaf(0.5f, tanha(0.5f * x), 0.5f);
}

__global__ void __launch_bounds__(NTH, 2)
lstm_seq2seq_kernel(const float* __restrict__ input,   // (T,B,1)
                    const float* __restrict__ speed,   // (B,1)
                    const float* __restrict__ target,  // (T,B,1)
                    const float* __restrict__ eWih,    // (256,1)
                    const float* __restrict__ eWhh,    // (256,64)
                    const float* __restrict__ ebih,    // (256)
                    const float* __restrict__ ebhh,    // (256)
                    const float* __restrict__ dWih,    // (260,1)
                    const float* __restrict__ dWhh,    // (260,65)
                    const float* __restrict__ dbih,    // (260)
                    const float* __restrict__ dbhh,    // (260)
                    const float* __restrict__ linW,    // (1,65)
                    const float* __restrict__ linb,    // (1)
                    const float* __restrict__ denW,    // (1,1)
                    const float* __restrict__ denb,    // (1)
                    float* __restrict__ out)           // (T,B,1)
{
    __shared__ __align__(16) float h_s[NB][HSTR];   // hidden state per batch
    __shared__ __align__(16) float g_s[NB][GD];     // gates (reused as c scratch at transition)
    __shared__ float x_s[2][NB];                    // double-buffered scalar inputs
    __shared__ __align__(16) float wx_s[4][HSTR];   // decoder leftover rows 256..259
    __shared__ float wih_x[4], b_x[4];
    __shared__ float lw_s[HD];
    __shared__ float sp_s[NB];

    const int tid  = threadIdx.x;
    const int lane = tid & 31;
    const int b0   = blockIdx.x * NB;
    const int r    = tid;              // gate row 0..255
    const int lb   = lane % NB;        // staggered batch start per lane

    // ---------------- encoder weights: row r of Whh into registers ----------------
    u64 wp[32];          // 64 weights as 32 packed f32x2 pairs
    {
        const ulonglong2* wr = (const ulonglong2*)(eWhh + r * HE);
        #pragma unroll
        for (int j = 0; j < 16; j++){ ulonglong2 v = wr[j]; wp[2*j] = v.x; wp[2*j+1] = v.y; }
    }
    float wih  = eWih[r];
    float bias = ebih[r] + ebhh[r];

    // zero hidden state
    for (int i = tid; i < NB * HSTR; i += NTH) ((float*)h_s)[i] = 0.0f;

    // encoder activation mapping: flat n = tid + 256*j over NB*HE = 448 items
    const int en0b = tid >> 6,          en0u = tid & 63;              // item 0 (all threads)
    const int en1b = (tid + NTH) >> 6,  en1u = tid & 63;              // item 1 (tid < 192)
    const bool e1v = (tid + NTH) < NB * HE;
    float c0 = 0.f, c1 = 0.f;

    const bool bvalid = (tid < NB) && (b0 + tid < BTOT);
    if (tid < NB) x_s[0][tid] = bvalid ? input[b0 + tid] : 0.0f;
    __syncthreads();

    // ================= encoder recurrence =================
    for (int t = 0; t < TS; t++){
        const float* xr = x_s[t & 1];
        float xnext = 0.0f;
        if (bvalid && t + 1 < TS) xnext = input[(t + 1) * BTOT + b0 + tid];

        // GEMM phase: gates[bb][r] = Whh[r,:] . h[bb,:] + wih*x[bb] + bias
        // lane-staggered batch order -> each LDS.128 wavefront reads 7 distinct rows
        #pragma unroll
        for (int j = 0; j < NB; j++){
            int bb = lb + j; if (bb >= NB) bb -= NB;
            const ulonglong2* hp = (const ulonglong2*)h_s[bb];
            u64 a0 = 0ull, a1 = 0ull;
            #pragma unroll
            for (int k = 0; k < 16; k++){
                ulonglong2 hv = hp[k];
                a0 = ffma2(hv.x, wp[2*k],     a0);
                a1 = ffma2(hv.y, wp[2*k + 1], a1);
            }
            float2 p = unpk(a0), q = unpk(a1);
            g_s[bb][r] = (p.x + p.y) + (q.x + q.y) + fmaf(wih, xr[bb], bias);
        }
        __syncthreads();

        // activation phase (PyTorch gate order i,f,g,o)
        {
            int bb; float ig, fg, gg, og, cc;
            bb = en0b;
            ig = g_s[bb][en0u]; fg = g_s[bb][HE+en0u]; gg = g_s[bb][2*HE+en0u]; og = g_s[bb][3*HE+en0u];
            cc = sigf(fg)*c0 + sigf(ig)*tanhf_(gg); c0 = cc;
            h_s[bb][en0u] = siga(og)*tanha(cc);
            if (e1v){
                bb = en1b;
                ig = g_s[bb][en1u]; fg = g_s[bb][HE+en1u]; gg = g_s[bb][2*HE+en1u]; og = g_s[bb][3*HE+en1u];
                cc = sigf(fg)*c1 + sigf(ig)*tanhf_(gg); c1 = cc;
                h_s[bb][en1u] = siga(og)*tanha(cc);
            }
        }
        if (tid < NB) x_s[(t + 1) & 1][tid] = xnext;
        __syncthreads();
    }

    // ================= encoder -> decoder transition =================
    // park encoder c in g_s (same (b,u) layout as encoder items)
    g_s[en0b][en0u] = c0;
    if (e1v) g_s[en1b][en1u] = c1;

    if (tid < NB){
        float sp = bvalid ? fmaf(speed[b0 + tid], denW[0], denb[0]) : 0.0f;
        sp_s[tid]     = sp;
        h_s[tid][HE]  = sp;     // 65th hidden element
        x_s[0][tid]   = 0.0f;   // teacher forcing: x_dec[0] = 0
    }
    if (tid < HD) lw_s[tid] = linW[tid];

    // decoder main-row weights (row r, 65 wide) into registers
    float wlast;
    {
        const float* wr = dWhh + r * HD;
        #pragma unroll
        for (int j = 0; j < 32; j++) wp[j] = pack2(wr[2*j], wr[2*j+1]);
        wlast = wr[64];
    }
    wih  = dWih[r];
    bias = dbih[r] + dbhh[r];

    // leftover rows 256..259 -> shared
    if (tid < 4){
        const float* wr = dWhh + (GE + tid) * HD;
        for (int k = 0; k < HD; k++) wx_s[tid][k] = wr[k];
        wih_x[tid] = dWih[GE + tid];
        b_x[tid]   = dbih[GE + tid] + dbhh[GE + tid];
    }
    __syncthreads();

    // decoder activation items: flat n = tid + 256*j over NB*HD = 455 items
    int   db[2], du[2];
    float dc[2];
    #pragma unroll
    for (int j = 0; j < 2; j++){
        int n = tid + NTH * j;
        bool v = (n < NB * HD);
        int bb = v ? (n / HD) : 0;
        int uu = v ? (n - bb * HD) : 0;
        db[j] = bb; du[j] = uu;
        dc[j] = v ? ((uu < HE) ? g_s[bb][uu] : sp_s[bb]) : 0.0f;
    }
    const bool d1v = (tid + NTH) < NB * HD;
    float lb_ = linb[0];
    __syncthreads();   // all c-init reads of g_s done before GEMM overwrites it

    // ================= decoder recurrence =================
    for (int t = 0; t < TS; t++){
        const float* xr = x_s[t & 1];

        // output projection for previous step's h (h_s stable during GEMM phase)
        if (bvalid && t > 0){
            float a0 = lb_, a1 = 0.f, a2 = 0.f, a3 = 0.f;
            #pragma unroll
            for (int k = 0; k < 64; k += 4){
                a0 = fmaf(lw_s[k  ], h_s[tid][k  ], a0);
                a1 = fmaf(lw_s[k+1], h_s[tid][k+1], a1);
                a2 = fmaf(lw_s[k+2], h_s[tid][k+2], a2);
                a3 = fmaf(lw_s[k+3], h_s[tid][k+3], a3);
            }
            a0 = fmaf(lw_s[64], h_s[tid][64], a0);
            out[(t - 1) * BTOT + b0 + tid] = (a0 + a1) + (a2 + a3);
        }

        float xnext = 0.0f;
        if (bvalid && t < TS - 1) xnext = target[t * BTOT + b0 + tid]; // x_dec[t+1] = target[t]

        // GEMM phase: main rows 0..255, lane-staggered batches
        #pragma unroll
        for (int j = 0; j < NB; j++){
            int bb = lb + j; if (bb >= NB) bb -= NB;
            const ulonglong2* hp = (const ulonglong2*)h_s[bb];
            u64 a0 = 0ull, a1 = 0ull;
            #pragma unroll
            for (int k = 0; k < 16; k++){
                ulonglong2 hv = hp[k];
                a0 = ffma2(hv.x, wp[2*k],     a0);
                a1 = ffma2(hv.y, wp[2*k + 1], a1);
            }
            float2 p = unpk(a0), q = unpk(a1);
            g_s[bb][r] = (p.x + p.y) + (q.x + q.y)
                       + fmaf(wlast, h_s[bb][HE], fmaf(wih, xr[bb], bias));
        }
        // leftover rows 256..259: last warp, 28 items (4 rows x 7 batches)
        if (tid >= NTH - 32){
            int i = tid - (NTH - 32);
            if (i < 4 * NB){
                int rr = i & 3, bb = i >> 2;
                float acc = fmaf(wih_x[rr], xr[bb], b_x[rr]);
                #pragma unroll
                for (int k = 0; k < HD; k++) acc = fmaf(wx_s[rr][k], h_s[bb][k], acc);
                g_s[bb][GE + rr] = acc;
            }
        }
        __syncthreads();

        // activation phase, H = 65
        #pragma unroll
        for (int j = 0; j < 2; j++){
            if (j == 0 || d1v){
                int bb = db[j], uu = du[j];
                float ig = g_s[bb][uu];
                float fg = g_s[bb][HD + uu];
                float gg = g_s[bb][2*HD + uu];
                float og = g_s[bb][3*HD + uu];
                float cc = sigf(fg) * dc[j] + sigf(ig) * tanhf_(gg);
                dc[j] = cc;
                h_s[bb][uu] = siga(og) * tanha(cc);
            }
        }
        if (tid < NB) x_s[(t + 1) & 1][tid] = xnext;
        __syncthreads();
    }

    // final output (t = TS-1)
    if (bvalid){
        float a0 = lb_, a1 = 0.f, a2 = 0.f, a3 = 0.f;
        #pragma unroll
        for (int k = 0; k < 64; k += 4){
            a0 = fmaf(lw_s[k  ], h_s[tid][k  ], a0);
            a1 = fmaf(lw_s[k+1], h_s[tid][k+1], a1);
            a2 = fmaf(lw_s[k+2], h_s[tid][k+2], a2);
            a3 = fmaf(lw_s[k+3], h_s[tid][k+3], a3);
        }
        a0 = fmaf(lw_s[64], h_s[tid][64], a0);
        out[(TS - 1) * BTOT + b0 + tid] = (a0 + a1) + (a2 + a3);
    }
}

extern "C" void kernel_launch(void* const* d_in, const int* in_sizes, int n_in,
                              void* d_out, int out_size)
{
    const float* input  = (const float*)d_in[0];
    const float* speed  = (const float*)d_in[1];
    const float* target = (const float*)d_in[2];
    const float* eWih   = (const float*)d_in[3];
    const float* eWhh   = (const float*)d_in[4];
    const float* ebih   = (const float*)d_in[5];
    const float* ebhh   = (const float*)d_in[6];
    const float* dWih   = (const float*)d_in[7];
    const float* dWhh   = (const float*)d_in[8];
    const float* dbih   = (const float*)d_in[9];
    const float* dbhh   = (const float*)d_in[10];
    const float* linW   = (const float*)d_in[11];
    const float* linb   = (const float*)d_in[12];
    const float* denW   = (const float*)d_in[13];
    const float* denb   = (const float*)d_in[14];
    float* outp = (float*)d_out;

    dim3 grid(NGRID);   // 296 blocks = 2 per SM on 148 SMs, balanced
    dim3 block(NTH);    // 256 threads
    lstm_seq2seq_kernel<<<grid, block>>>(input, speed, target,
                                         eWih, eWhh, ebih, ebhh,
                                         dWih, dWhh, dbih, dbhh,
                                         linW, linb, denW, denb, outp);
}

// round 5
// speedup vs baseline: 1.9901x; 1.9901x over previous
#include <cuda_runtime.h>

// Problem constants
#define TS   1000
#define BTOT 2048
#define HE   64     // encoder hidden
#define HD   65     // decoder hidden
#define GE   256    // 4*HE
#define GD   260    // 4*HD
#define NB   14     // batch elements per block (148 blocks -> 1 per SM, balanced)
#define NGRID 148
#define NTH  256    // threads per block
#define HSTR 68     // h row stride (16B-aligned rows)

typedef unsigned long long u64;

__device__ __forceinline__ u64 pack2(float lo, float hi){
    u64 r; asm("mov.b64 %0, {%1, %2};" : "=l"(r) : "f"(lo), "f"(hi)); return r;
}
__device__ __forceinline__ float2 unpk(u64 v){
    float2 f; asm("mov.b64 {%0, %1}, %2;" : "=f"(f.x), "=f"(f.y) : "l"(v)); return f;
}
__device__ __forceinline__ u64 ffma2(u64 a, u64 b, u64 c){
    u64 d; asm("fma.rn.f32x2 %0, %1, %2, %3;" : "=l"(d) : "l"(a), "l"(b), "l"(c)); return d;
}
// accurate sigmoid (recurrent path: i, f gates)
__device__ __forceinline__ float sigf(float x){
    return __fdividef(1.0f, 1.0f + __expf(-x));
}
// accurate tanh (recurrent path: g gate)
__device__ __forceinline__ float tanhf_(float x){
    return fmaf(2.0f, sigf(2.0f * x), -1.0f);
}
// fast tanh via MUFU.TANH (non-recurrent path only)
__device__ __forceinline__ float tanha(float x){
    float y; asm("tanh.approx.f32 %0, %1;" : "=f"(y) : "f"(x)); return y;
}
// fast sigmoid via MUFU.TANH (o gate only)
__device__ __forceinline__ float siga(float x){
    return fmaf(0.5f, tanha(0.5f * x), 0.5f);
}

__global__ void __launch_bounds__(NTH, 1)
lstm_seq2seq_kernel(const float* __restrict__ input,   // (T,B,1)
                    const float* __restrict__ speed,   // (B,1)
                    const float* __restrict__ target,  // (T,B,1)
                    const float* __restrict__ eWih,    // (256,1)
                    const float* __restrict__ eWhh,    // (256,64)
                    const float* __restrict__ ebih,    // (256)
                    const float* __restrict__ ebhh,    // (256)
                    const float* __restrict__ dWih,    // (260,1)
                    const float* __restrict__ dWhh,    // (260,65)
                    const float* __restrict__ dbih,    // (260)
                    const float* __restrict__ dbhh,    // (260)
                    const float* __restrict__ linW,    // (1,65)
                    const float* __restrict__ linb,    // (1)
                    const float* __restrict__ denW,    // (1,1)
                    const float* __restrict__ denb,    // (1)
                    float* __restrict__ out)           // (T,B,1)
{
    __shared__ __align__(16) float h_s[NB][HSTR];   // hidden state per batch
    __shared__ __align__(16) float g_s[NB][GD];     // gates (reused as c scratch at transition)
    __shared__ float x_s[2][NB];                    // double-buffered scalar inputs
    __shared__ __align__(16) float wx_s[4][HSTR];   // decoder leftover rows 256..259
    __shared__ float wih_x[4], b_x[4];
    __shared__ float lw_s[HD];
    __shared__ float sp_s[NB];

    const int tid = threadIdx.x;
    const int b0  = blockIdx.x * NB;
    const int r   = tid & 127;         // base gate row; thread owns rows r and r+128
    const int grp = tid >> 7;          // batch half: 0 -> batches 0..6, 1 -> 7..13
    const int bA  = grp * 7;

    // ---------------- encoder weights: rows r and r+128 into registers ----------------
    u64 wpA[32], wpB[32];
    {
        const ulonglong2* wrA = (const ulonglong2*)(eWhh + r * HE);
        const ulonglong2* wrB = (const ulonglong2*)(eWhh + (r + 128) * HE);
        #pragma unroll
        for (int j = 0; j < 16; j++){
            ulonglong2 va = wrA[j]; wpA[2*j] = va.x; wpA[2*j+1] = va.y;
            ulonglong2 vb = wrB[j]; wpB[2*j] = vb.x; wpB[2*j+1] = vb.y;
        }
    }
    float wihA  = eWih[r],           wihB  = eWih[r + 128];
    float biasA = ebih[r] + ebhh[r], biasB = ebih[r + 128] + ebhh[r + 128];

    // zero hidden state
    for (int i = tid; i < NB * HSTR; i += NTH) ((float*)h_s)[i] = 0.0f;

    // encoder activation mapping: flat n = tid + 256*j over NB*HE = 896 items
    float c_e[4] = {0.f, 0.f, 0.f, 0.f};

    const bool bvalid = (tid < NB) && (b0 + tid < BTOT);
    if (tid < NB) x_s[0][tid] = bvalid ? input[b0 + tid] : 0.0f;
    __syncthreads();

    // ================= encoder recurrence =================
    for (int t = 0; t < TS; t++){
        const float* xr = x_s[t & 1];
        float xnext = 0.0f;
        if (bvalid && t + 1 < TS) xnext = input[(t + 1) * BTOT + b0 + tid];

        // GEMM phase: rows r, r+128 over batches bA..bA+6 (broadcast h reads)
        #pragma unroll
        for (int j = 0; j < 7; j++){
            const int bb = bA + j;
            const ulonglong2* hp = (const ulonglong2*)h_s[bb];
            u64 a0 = 0ull, a1 = 0ull, d0 = 0ull, d1 = 0ull;
            #pragma unroll
            for (int k = 0; k < 16; k++){
                ulonglong2 hv = hp[k];
                a0 = ffma2(hv.x, wpA[2*k],     a0);
                a1 = ffma2(hv.y, wpA[2*k + 1], a1);
                d0 = ffma2(hv.x, wpB[2*k],     d0);
                d1 = ffma2(hv.y, wpB[2*k + 1], d1);
            }
            float2 p = unpk(a0), q = unpk(a1);
            float2 s = unpk(d0), w = unpk(d1);
            g_s[bb][r]       = (p.x + p.y) + (q.x + q.y) + fmaf(wihA, xr[bb], biasA);
            g_s[bb][r + 128] = (s.x + s.y) + (w.x + w.y) + fmaf(wihB, xr[bb], biasB);
        }
        __syncthreads();

        // activation phase (PyTorch gate order i,f,g,o), items n = tid + 256*j
        #pragma unroll
        for (int j = 0; j < 4; j++){
            int n = tid + NTH * j;
            if (j < 3 || n < NB * HE){
                int bb = n >> 6, uu = n & 63;
                float ig = g_s[bb][uu];
                float fg = g_s[bb][HE + uu];
                float gg = g_s[bb][2*HE + uu];
                float og = g_s[bb][3*HE + uu];
                float cc = sigf(fg) * c_e[j] + sigf(ig) * tanhf_(gg);
                c_e[j] = cc;
                h_s[bb][uu] = siga(og) * tanha(cc);
            }
        }
        if (tid < NB) x_s[(t + 1) & 1][tid] = xnext;
        __syncthreads();
    }

    // ================= encoder -> decoder transition =================
    // park encoder c in g_s (same (b,u) layout as encoder items)
    #pragma unroll
    for (int j = 0; j < 4; j++){
        int n = tid + NTH * j;
        if (j < 3 || n < NB * HE){
            int bb = n >> 6, uu = n & 63;
            g_s[bb][uu] = c_e[j];
        }
    }

    if (tid < NB){
        float sp = bvalid ? fmaf(speed[b0 + tid], denW[0], denb[0]) : 0.0f;
        sp_s[tid]     = sp;
        h_s[tid][HE]  = sp;     // 65th hidden element
        x_s[0][tid]   = 0.0f;   // teacher forcing: x_dec[0] = 0
    }
    if (tid < HD) lw_s[tid] = linW[tid];

    // decoder weights: rows r and r+128 (65 wide) into registers
    float wlastA, wlastB;
    {
        const float* wrA = dWhh + r * HD;
        const float* wrB = dWhh + (r + 128) * HD;
        #pragma unroll
        for (int j = 0; j < 32; j++){
            wpA[j] = pack2(wrA[2*j], wrA[2*j+1]);
            wpB[j] = pack2(wrB[2*j], wrB[2*j+1]);
        }
        wlastA = wrA[64]; wlastB = wrB[64];
    }
    wihA  = dWih[r];                 wihB  = dWih[r + 128];
    biasA = dbih[r] + dbhh[r];       biasB = dbih[r + 128] + dbhh[r + 128];

    // leftover rows 256..259 -> shared
    if (tid < 4){
        const float* wr = dWhh + (GE + tid) * HD;
        for (int k = 0; k < HD; k++) wx_s[tid][k] = wr[k];
        wih_x[tid] = dWih[GE + tid];
        b_x[tid]   = dbih[GE + tid] + dbhh[GE + tid];
    }
    __syncthreads();

    // decoder activation items: flat n = tid + 256*j over NB*HD = 910 items
    int   db[4], du[4];
    float dc[4];
    #pragma unroll
    for (int j = 0; j < 4; j++){
        int n = tid + NTH * j;
        bool v = (n < NB * HD);
        int bb = v ? (n / HD) : 0;
        int uu = v ? (n - bb * HD) : 0;
        db[j] = bb; du[j] = uu;
        dc[j] = v ? ((uu < HE) ? g_s[bb][uu] : sp_s[bb]) : 0.0f;
    }
    float lb_ = linb[0];
    __syncthreads();   // all c-init reads of g_s done before GEMM overwrites it

    // ================= decoder recurrence =================
    for (int t = 0; t < TS; t++){
        const float* xr = x_s[t & 1];

        // output projection for previous step's h (h_s stable during GEMM phase)
        if (bvalid && t > 0){
            float a0 = lb_, a1 = 0.f, a2 = 0.f, a3 = 0.f;
            #pragma unroll
            for (int k = 0; k < 64; k += 4){
                a0 = fmaf(lw_s[k  ], h_s[tid][k  ], a0);
                a1 = fmaf(lw_s[k+1], h_s[tid][k+1], a1);
                a2 = fmaf(lw_s[k+2], h_s[tid][k+2], a2);
                a3 = fmaf(lw_s[k+3], h_s[tid][k+3], a3);
            }
            a0 = fmaf(lw_s[64], h_s[tid][64], a0);
            out[(t - 1) * BTOT + b0 + tid] = (a0 + a1) + (a2 + a3);
        }

        float xnext = 0.0f;
        if (bvalid && t < TS - 1) xnext = target[t * BTOT + b0 + tid]; // x_dec[t+1] = target[t]

        // GEMM phase: rows r, r+128 over batches bA..bA+6
        #pragma unroll
        for (int j = 0; j < 7; j++){
            const int bb = bA + j;
            const ulonglong2* hp = (const ulonglong2*)h_s[bb];
            u64 a0 = 0ull, a1 = 0ull, d0 = 0ull, d1 = 0ull;
            #pragma unroll
            for (int k = 0; k < 16; k++){
                ulonglong2 hv = hp[k];
                a0 = ffma2(hv.x, wpA[2*k],     a0);
                a1 = ffma2(hv.y, wpA[2*k + 1], a1);
                d0 = ffma2(hv.x, wpB[2*k],     d0);
                d1 = ffma2(hv.y, wpB[2*k + 1], d1);
            }
            float hlast = h_s[bb][HE];
            float2 p = unpk(a0), q = unpk(a1);
            float2 s = unpk(d0), w = unpk(d1);
            g_s[bb][r]       = (p.x + p.y) + (q.x + q.y)
                             + fmaf(wlastA, hlast, fmaf(wihA, xr[bb], biasA));
            g_s[bb][r + 128] = (s.x + s.y) + (w.x + w.y)
                             + fmaf(wlastB, hlast, fmaf(wihB, xr[bb], biasB));
        }
        // leftover rows 256..259: threads 192..247, 56 items (4 rows x 14 batches)
        if (tid >= 192){
            int i = tid - 192;
            if (i < 4 * NB){
                int rr = i & 3, bb = i >> 2;
                float acc = fmaf(wih_x[rr], xr[bb], b_x[rr]);
                #pragma unroll
                for (int k = 0; k < HD; k++) acc = fmaf(wx_s[rr][k], h_s[bb][k], acc);
                g_s[bb][GE + rr] = acc;
            }
        }
        __syncthreads();

        // activation phase, H = 65
        #pragma unroll
        for (int j = 0; j < 4; j++){
            if (j < 3 || tid + NTH * j < NB * HD){
                int bb = db[j], uu = du[j];
                float ig = g_s[bb][uu];
                float fg = g_s[bb][HD + uu];
                float gg = g_s[bb][2*HD + uu];
                float og = g_s[bb][3*HD + uu];
                float cc = sigf(fg) * dc[j] + sigf(ig) * tanhf_(gg);
                dc[j] = cc;
                h_s[bb][uu] = siga(og) * tanha(cc);
            }
        }
        if (tid < NB) x_s[(t + 1) & 1][tid] = xnext;
        __syncthreads();
    }

    // final output (t = TS-1)
    if (bvalid){
        float a0 = lb_, a1 = 0.f, a2 = 0.f, a3 = 0.f;
        #pragma unroll
        for (int k = 0; k < 64; k += 4){
            a0 = fmaf(lw_s[k  ], h_s[tid][k  ], a0);
            a1 = fmaf(lw_s[k+1], h_s[tid][k+1], a1);
            a2 = fmaf(lw_s[k+2], h_s[tid][k+2], a2);
            a3 = fmaf(lw_s[k+3], h_s[tid][k+3], a3);
        }
        a0 = fmaf(lw_s[64], h_s[tid][64], a0);
        out[(TS - 1) * BTOT + b0 + tid] = (a0 + a1) + (a2 + a3);
    }
}

extern "C" void kernel_launch(void* const* d_in, const int* in_sizes, int n_in,
                              void* d_out, int out_size)
{
    const float* input  = (const float*)d_in[0];
    const float* speed  = (const float*)d_in[1];
    const float* target = (const float*)d_in[2];
    const float* eWih   = (const float*)d_in[3];
    const float* eWhh   = (const float*)d_in[4];
    const float* ebih   = (const float*)d_in[5];
    const float* ebhh   = (const float*)d_in[6];
    const float* dWih   = (const float*)d_in[7];
    const float* dWhh   = (const float*)d_in[8];
    const float* dbih   = (const float*)d_in[9];
    const float* dbhh   = (const float*)d_in[10];
    const float* linW   = (const float*)d_in[11];
    const float* linb   = (const float*)d_in[12];
    const float* denW   = (const float*)d_in[13];
    const float* denb   = (const float*)d_in[14];
    float* outp = (float*)d_out;

    dim3 grid(NGRID);   // 148 blocks = 1 per SM, perfectly balanced
    dim3 block(NTH);    // 256 threads
    lstm_seq2seq_kernel<<<grid, block>>>(input, speed, target,
                                         eWih, eWhh, ebih, ebhh,
                                         dWih, dWhh, dbih, dbhh,
                                         linW, linb, denW, denb, outp);
}